// round 6
// baseline (speedup 1.0000x reference)
#include <cuda_runtime.h>
#include <cstdint>

#define T_STEPS 256
#define BATCH   64
#define INDIM   1024
#define HID     1024
#define G4      4096
#define NCTA2   128   // recurrent grid, all co-resident (1 CTA/SM)
#define UPC     8     // hidden units per recurrent CTA
#define KC      128   // k-chunk for h staging

// ---------------- scratch (static device globals; no allocs allowed) --------
__device__ float    g_xg[(size_t)T_STEPS * BATCH * G4];  // 256 MiB input projection
__device__ float    g_h[2][HID][BATCH];                  // TRANSPOSED [k][b], double buffered
__device__ unsigned g_bar_cnt;
__device__ unsigned g_bar_gen;
__device__ unsigned g_flags[NCTA2];                      // flag-array barrier

// ---------------- legacy atomic barrier (used once at start) ----------------
__device__ __forceinline__ void grid_barrier_atomic(unsigned nctas) {
    __syncthreads();
    __threadfence();
    if (threadIdx.x == 0) {
        unsigned gen = *(volatile unsigned*)&g_bar_gen;
        unsigned t = atomicAdd(&g_bar_cnt, 1u);
        if (t == nctas - 1u) {
            *(volatile unsigned*)&g_bar_cnt = 0u;
            __threadfence();
            atomicAdd(&g_bar_gen, 1u);
        } else {
            while (*(volatile unsigned*)&g_bar_gen == gen) { __nanosleep(64); }
        }
        __threadfence();
    }
    __syncthreads();
}

// ---------------- flag-array barrier (per-step; val monotonic in step) ------
// Release/acquire semantics: the release-store of this CTA's flag orders all
// of its prior global stores; the acquire-load poll orders subsequent reads.
__device__ __forceinline__ void grid_barrier_flags(int cta, unsigned val) {
    __syncthreads();          // all threads of this CTA done with their stores
    if (threadIdx.x == 0) {
        asm volatile("st.global.release.gpu.u32 [%0], %1;"
                     :: "l"(&g_flags[cta]), "r"(val));
    }
    if (threadIdx.x < NCTA2) {
        unsigned v;
        do {
            asm volatile("ld.global.acquire.gpu.u32 %0, [%1];"
                         : "=r"(v) : "l"(&g_flags[threadIdx.x]));
        } while (v < val);
    }
    __syncthreads();
}

// ---------------- cp.async helpers ------------------------------------------
__device__ __forceinline__ void cp_async_cg16(void* dst_smem, const void* src) {
    unsigned d = (unsigned)__cvta_generic_to_shared(dst_smem);
    asm volatile("cp.async.cg.shared.global [%0], [%1], 16;\n" :: "r"(d), "l"(src));
}
__device__ __forceinline__ void cp_async_commit() {
    asm volatile("cp.async.commit_group;\n");
}
template <int N>
__device__ __forceinline__ void cp_async_wait() {
    asm volatile("cp.async.wait_group %0;\n" :: "n"(N));
}

// ---------------- Phase 1: xg = (x * W_ih^T + b_ih) + b_hh ------------------
// EXACT ORDER CONTRACT: per output element, single fp32 accumulator,
// sequential fused-FMA over k = 0..1023 ascending, then +b_ih, then +b_hh.
// (Scalar FFMA only — packed f32x2 produced garbage on sm_100a in round 5.)
#define BM 128
#define BN 128
#define BK 8

__global__ void __launch_bounds__(256, 2) gemm_xproj(
    const float* __restrict__ x, const float* __restrict__ Wih,
    const float* __restrict__ bih, const float* __restrict__ bhh)
{
    __shared__ float As[2][BK][132];
    __shared__ float Bs[2][BK][132];

    const int m0  = blockIdx.y * BM;
    const int n0  = blockIdx.x * BN;
    const int tid = threadIdx.x;
    const int tm  = tid >> 4;       // 0..15
    const int tn  = tid & 15;       // 0..15
    const int lk  = tid & 7;        // k lane for tile loads
    const int lr  = tid >> 3;       // row lane (0..31)

    float acc[8][8];
#pragma unroll
    for (int i = 0; i < 8; i++)
#pragma unroll
        for (int j = 0; j < 8; j++) acc[i][j] = 0.0f;

    float ra[4], rb[4];
#pragma unroll
    for (int p = 0; p < 4; p++) {
        ra[p] = x  [(size_t)(m0 + lr + p * 32) * INDIM + lk];
        rb[p] = Wih[(size_t)(n0 + lr + p * 32) * INDIM + lk];
    }

    for (int it = 0; it < INDIM / BK; it++) {
        const int buf = it & 1;
#pragma unroll
        for (int p = 0; p < 4; p++) {
            As[buf][lk][lr + p * 32] = ra[p];
            Bs[buf][lk][lr + p * 32] = rb[p];
        }
        __syncthreads();

        if (it + 1 < INDIM / BK) {
            const int k0 = (it + 1) * BK;
#pragma unroll
            for (int p = 0; p < 4; p++) {
                ra[p] = x  [(size_t)(m0 + lr + p * 32) * INDIM + k0 + lk];
                rb[p] = Wih[(size_t)(n0 + lr + p * 32) * INDIM + k0 + lk];
            }
        }

        // strictly sequential over k (ascending), single accumulator, FFMA
#pragma unroll
        for (int k = 0; k < BK; k++) {
            float4 a0 = *(const float4*)&As[buf][k][tm * 8];
            float4 a1 = *(const float4*)&As[buf][k][tm * 8 + 4];
            float4 b0 = *(const float4*)&Bs[buf][k][tn * 8];
            float4 b1 = *(const float4*)&Bs[buf][k][tn * 8 + 4];
            float av[8] = {a0.x, a0.y, a0.z, a0.w, a1.x, a1.y, a1.z, a1.w};
            float bv[8] = {b0.x, b0.y, b0.z, b0.w, b1.x, b1.y, b1.z, b1.w};
#pragma unroll
            for (int i = 0; i < 8; i++)
#pragma unroll
                for (int j = 0; j < 8; j++)
                    acc[i][j] = __fmaf_rn(av[i], bv[j], acc[i][j]);
        }
    }

    // epilogue: (acc + b_ih) + b_hh  — two separate rounded adds, ref order
    float bi[8], bh[8];
#pragma unroll
    for (int j = 0; j < 8; j++) {
        int n = n0 + tn * 8 + j;
        bi[j] = bih[n];
        bh[j] = bhh[n];
    }
#pragma unroll
    for (int i = 0; i < 8; i++) {
        float v[8];
#pragma unroll
        for (int j = 0; j < 8; j++)
            v[j] = __fadd_rn(__fadd_rn(acc[i][j], bi[j]), bh[j]);
        size_t row = (size_t)(m0 + tm * 8 + i) * G4 + (n0 + tn * 8);
        *(float4*)&g_xg[row]     = make_float4(v[0], v[1], v[2], v[3]);
        *(float4*)&g_xg[row + 4] = make_float4(v[4], v[5], v[6], v[7]);
    }
}

// ---------------- Phase 2: persistent recurrent kernel ----------------------
// W_hh slice persistent in smem; h transposed [k][b] in global, staged per
// 128-k chunk via cp.async double buffering. Scalar FFMA inner loop (proven).
// EXACT ORDER CONTRACT: hg = sequential FFMA k=0..1023 from 0.0f;
// z = xg + hg (one rounded add). Gate math exact 0/1-integer arithmetic.
#define SM_W    (HID * 33)            // 33792 floats
#define SM_HS   (KC * BATCH)          // 8192 floats per buffer
#define SM_SPK  (BATCH * 33)          // 2112 floats
#define SMEM_BYTES ((SM_W + 2 * SM_HS + SM_SPK) * 4)   // 209152 B

extern __shared__ float sm[];

__global__ void __launch_bounds__(256, 1) spiking_lstm_rec(
    const float* __restrict__ h0, const float* __restrict__ c0,
    const float* __restrict__ Whh, float* __restrict__ y)
{
    float* w_sm = sm;                       // w_sm[k*33 + col]
    float* hs   = sm + SM_W;                // hs[buf*SM_HS + k_local*64 + b]
    float* spk  = sm + SM_W + 2 * SM_HS;    // spk[b*33 + col]

    const int cta  = blockIdx.x;
    const int u0   = cta * UPC;
    const int tid  = threadIdx.x;
    const int col  = tid & 31;     // gate = col/8, u_local = col%8
    const int bgrp = tid >> 5;     // batch rows 8*bgrp..8*bgrp+7
    const int ub   = tid & 7;
    const int bb   = tid >> 3;     // 0..31

    // reset flag barrier for this graph replay (ordered before atomic barrier)
    if (tid == 0) {
        asm volatile("st.global.cg.u32 [%0], %1;" :: "l"(&g_flags[cta]), "r"(0u));
    }

    // ---- load W_hh slice into persistent smem (one time) ----
    {
        const int wc  = tid >> 3;                         // col 0..31
        const int sub = tid & 7;
        const int wrow = (wc >> 3) * HID + u0 + (wc & 7); // W_hh row for col wc
        const float* wp = Whh + (size_t)wrow * HID;
        for (int k0 = sub * 4; k0 < HID; k0 += 32) {
            float4 v = *(const float4*)&wp[k0];
            w_sm[(k0 + 0) * 33 + wc] = v.x;
            w_sm[(k0 + 1) * 33 + wc] = v.y;
            w_sm[(k0 + 2) * 33 + wc] = v.z;
            w_sm[(k0 + 3) * 33 + wc] = v.w;
        }
    }

    // ---- init c and transposed h[0] ----
    float c_a = c0[(size_t)bb * HID + u0 + ub];
    float c_b = c0[(size_t)(bb + 32) * HID + u0 + ub];
    __stcg(&g_h[0][u0 + ub][bb],      h0[(size_t)bb * HID + u0 + ub]);
    __stcg(&g_h[0][u0 + ub][bb + 32], h0[(size_t)(bb + 32) * HID + u0 + ub]);
    grid_barrier_atomic(NCTA2);   // h[0] + flag resets visible; w_sm ready

    for (int s = 0; s < T_STEPS; s++) {
        const float* __restrict__ hprev = &g_h[s & 1][0][0];

        // xg values (consumed at end of step; loads overlap all compute)
        float xgv[8];
        {
            size_t base = (size_t)s * BATCH * G4 + (size_t)((col >> 3) * HID + u0 + (col & 7));
#pragma unroll
            for (int r = 0; r < 8; r++)
                xgv[r] = g_xg[base + (size_t)(bgrp * 8 + r) * G4];
        }

        float acc[8];
#pragma unroll
        for (int r = 0; r < 8; r++) acc[r] = 0.0f;

        // prefetch chunk 0 (each thread copies 32 contiguous floats)
        {
            const float* src = hprev + tid * 32;
            float* dst = hs + tid * 32;
#pragma unroll
            for (int j = 0; j < 8; j++)
                cp_async_cg16(dst + j * 4, src + j * 4);
            cp_async_commit();
        }

        for (int ic = 0; ic < HID / KC; ic++) {
            if (ic + 1 < HID / KC) {
                const float* src = hprev + (ic + 1) * KC * BATCH + tid * 32;
                float* dst = hs + ((ic + 1) & 1) * SM_HS + tid * 32;
#pragma unroll
                for (int j = 0; j < 8; j++)
                    cp_async_cg16(dst + j * 4, src + j * 4);
                cp_async_commit();
                cp_async_wait<1>();   // chunk ic complete, ic+1 in flight
            } else {
                cp_async_wait<0>();
            }
            __syncthreads();

            const float* wk = w_sm + (ic * KC) * 33 + col;
            const float* hb = hs + (ic & 1) * SM_HS + bgrp * 8;
#pragma unroll 8
            for (int k = 0; k < KC; k++) {
                float w = wk[k * 33];
                float4 p = *(const float4*)&hb[k * 64];
                float4 q = *(const float4*)&hb[k * 64 + 4];
                acc[0] = __fmaf_rn(p.x, w, acc[0]);
                acc[1] = __fmaf_rn(p.y, w, acc[1]);
                acc[2] = __fmaf_rn(p.z, w, acc[2]);
                acc[3] = __fmaf_rn(p.w, w, acc[3]);
                acc[4] = __fmaf_rn(q.x, w, acc[4]);
                acc[5] = __fmaf_rn(q.y, w, acc[5]);
                acc[6] = __fmaf_rn(q.z, w, acc[6]);
                acc[7] = __fmaf_rn(q.w, w, acc[7]);
            }
            __syncthreads();   // protects buffer reuse by next prefetch
        }

        // z = xg + hg; spike
#pragma unroll
        for (int r = 0; r < 8; r++) {
            float z = __fadd_rn(xgv[r], acc[r]);
            spk[(bgrp * 8 + r) * 33 + col] = (z >= 0.0f) ? 1.0f : 0.0f;
        }
        __syncthreads();

        // gate update: c' = f*c + i*g ; h' = o*c'   (exact 0/1-integer math)
        {
            float* hnext = &g_h[(s + 1) & 1][0][0];

            float i1 = spk[bb * 33 + ub],      f1 = spk[bb * 33 + 8 + ub];
            float g1 = spk[bb * 33 + 16 + ub], o1 = spk[bb * 33 + 24 + ub];
            c_a = __fadd_rn(__fmul_rn(f1, c_a), __fmul_rn(i1, g1));
            float ha = __fmul_rn(o1, c_a);
            y[((size_t)s * BATCH + bb) * HID + u0 + ub] = ha;
            __stcg(&hnext[(size_t)(u0 + ub) * BATCH + bb], ha);

            float i2 = spk[(bb + 32) * 33 + ub],      f2 = spk[(bb + 32) * 33 + 8 + ub];
            float g2 = spk[(bb + 32) * 33 + 16 + ub], o2 = spk[(bb + 32) * 33 + 24 + ub];
            c_b = __fadd_rn(__fmul_rn(f2, c_b), __fmul_rn(i2, g2));
            float hb2 = __fmul_rn(o2, c_b);
            y[((size_t)s * BATCH + bb + 32) * HID + u0 + ub] = hb2;
            __stcg(&hnext[(size_t)(u0 + ub) * BATCH + bb + 32], hb2);
        }

        grid_barrier_flags(cta, (unsigned)(s + 1));
    }
}

// ---------------- launch ----------------------------------------------------
extern "C" void kernel_launch(void* const* d_in, const int* in_sizes, int n_in,
                              void* d_out, int out_size) {
    const float* x   = (const float*)d_in[0];   // [T,B,I]
    const float* h0  = (const float*)d_in[1];   // [B,H]
    const float* c0  = (const float*)d_in[2];   // [B,H]
    const float* Wih = (const float*)d_in[3];   // [4H,I]
    const float* bih = (const float*)d_in[4];   // [4H]
    const float* Whh = (const float*)d_in[5];   // [4H,H]
    const float* bhh = (const float*)d_in[6];   // [4H]
    float* y = (float*)d_out;                   // [T,B,H]

    cudaFuncSetAttribute(spiking_lstm_rec,
                         cudaFuncAttributeMaxDynamicSharedMemorySize, SMEM_BYTES);

    gemm_xproj<<<dim3(G4 / BN, (T_STEPS * BATCH) / BM), 256>>>(x, Wih, bih, bhh);
    spiking_lstm_rec<<<NCTA2, 256, SMEM_BYTES>>>(h0, c0, Whh, y);
}

// round 8
// speedup vs baseline: 1.1435x; 1.1435x over previous
#include <cuda_runtime.h>
#include <cstdint>

#define T_STEPS 256
#define BATCH   64
#define INDIM   1024
#define HID     1024
#define G4      4096
#define NCTA2   128   // recurrent grid, all co-resident (1 CTA/SM)
#define UPC     8     // hidden units per recurrent CTA
#define KC      128   // k-chunk for h staging

// ---------------- scratch (static device globals; no allocs allowed) --------
__device__ float    g_xg[(size_t)T_STEPS * BATCH * G4];  // 256 MiB input projection
__device__ float    g_h[2][HID][BATCH];                  // TRANSPOSED [k][b], double buffered
__device__ unsigned g_bar_cnt;
__device__ unsigned g_bar_gen;

// ---------------- grid-wide atomic barrier (round-4 proven) -----------------
__device__ __forceinline__ void grid_barrier_atomic(unsigned nctas) {
    __syncthreads();
    __threadfence();
    if (threadIdx.x == 0) {
        unsigned gen = *(volatile unsigned*)&g_bar_gen;
        unsigned t = atomicAdd(&g_bar_cnt, 1u);
        if (t == nctas - 1u) {
            *(volatile unsigned*)&g_bar_cnt = 0u;
            __threadfence();
            atomicAdd(&g_bar_gen, 1u);
        } else {
            while (*(volatile unsigned*)&g_bar_gen == gen) { __nanosleep(64); }
        }
        __threadfence();
    }
    __syncthreads();
}

// ---------------- cp.async helpers ------------------------------------------
__device__ __forceinline__ void cp_async_cg16(void* dst_smem, const void* src) {
    unsigned d = (unsigned)__cvta_generic_to_shared(dst_smem);
    asm volatile("cp.async.cg.shared.global [%0], [%1], 16;\n" :: "r"(d), "l"(src));
}
__device__ __forceinline__ void cp_async_commit() {
    asm volatile("cp.async.commit_group;\n");
}
template <int N>
__device__ __forceinline__ void cp_async_wait() {
    asm volatile("cp.async.wait_group %0;\n" :: "n"(N));
}

// ---------------- Phase 1: xg = (x * W_ih^T + b_ih) + b_hh ------------------
// EXACT ORDER CONTRACT: per output element, single fp32 accumulator,
// sequential fused-FMA over k = 0..1023 ascending, then +b_ih, then +b_hh.
// (Scalar FFMA only — packed f32x2 is broken for this on sm_100a, r5.)
#define BM 128
#define BN 128
#define BK 8

__global__ void __launch_bounds__(256, 2) gemm_xproj(
    const float* __restrict__ x, const float* __restrict__ Wih,
    const float* __restrict__ bih, const float* __restrict__ bhh)
{
    __shared__ float As[2][BK][132];
    __shared__ float Bs[2][BK][132];

    const int m0  = blockIdx.y * BM;
    const int n0  = blockIdx.x * BN;
    const int tid = threadIdx.x;
    const int tm  = tid >> 4;       // 0..15
    const int tn  = tid & 15;       // 0..15
    const int lk  = tid & 7;        // k lane for tile loads
    const int lr  = tid >> 3;       // row lane (0..31)

    float acc[8][8];
#pragma unroll
    for (int i = 0; i < 8; i++)
#pragma unroll
        for (int j = 0; j < 8; j++) acc[i][j] = 0.0f;

    float ra[4], rb[4];
#pragma unroll
    for (int p = 0; p < 4; p++) {
        ra[p] = x  [(size_t)(m0 + lr + p * 32) * INDIM + lk];
        rb[p] = Wih[(size_t)(n0 + lr + p * 32) * INDIM + lk];
    }

    for (int it = 0; it < INDIM / BK; it++) {
        const int buf = it & 1;
#pragma unroll
        for (int p = 0; p < 4; p++) {
            As[buf][lk][lr + p * 32] = ra[p];
            Bs[buf][lk][lr + p * 32] = rb[p];
        }
        __syncthreads();

        if (it + 1 < INDIM / BK) {
            const int k0 = (it + 1) * BK;
#pragma unroll
            for (int p = 0; p < 4; p++) {
                ra[p] = x  [(size_t)(m0 + lr + p * 32) * INDIM + k0 + lk];
                rb[p] = Wih[(size_t)(n0 + lr + p * 32) * INDIM + k0 + lk];
            }
        }

        // strictly sequential over k (ascending), single accumulator, FFMA
#pragma unroll
        for (int k = 0; k < BK; k++) {
            float4 a0 = *(const float4*)&As[buf][k][tm * 8];
            float4 a1 = *(const float4*)&As[buf][k][tm * 8 + 4];
            float4 b0 = *(const float4*)&Bs[buf][k][tn * 8];
            float4 b1 = *(const float4*)&Bs[buf][k][tn * 8 + 4];
            float av[8] = {a0.x, a0.y, a0.z, a0.w, a1.x, a1.y, a1.z, a1.w};
            float bv[8] = {b0.x, b0.y, b0.z, b0.w, b1.x, b1.y, b1.z, b1.w};
#pragma unroll
            for (int i = 0; i < 8; i++)
#pragma unroll
                for (int j = 0; j < 8; j++)
                    acc[i][j] = __fmaf_rn(av[i], bv[j], acc[i][j]);
        }
    }

    // epilogue: (acc + b_ih) + b_hh  — two separate rounded adds, ref order
    float bi[8], bh[8];
#pragma unroll
    for (int j = 0; j < 8; j++) {
        int n = n0 + tn * 8 + j;
        bi[j] = bih[n];
        bh[j] = bhh[n];
    }
#pragma unroll
    for (int i = 0; i < 8; i++) {
        float v[8];
#pragma unroll
        for (int j = 0; j < 8; j++)
            v[j] = __fadd_rn(__fadd_rn(acc[i][j], bi[j]), bh[j]);
        size_t row = (size_t)(m0 + tm * 8 + i) * G4 + (n0 + tn * 8);
        *(float4*)&g_xg[row]     = make_float4(v[0], v[1], v[2], v[3]);
        *(float4*)&g_xg[row + 4] = make_float4(v[4], v[5], v[6], v[7]);
    }
}

// ---------------- Phase 2: persistent recurrent kernel ----------------------
// W_hh slice persistent in smem. PER-WARP h staging: warp w consumes only
// h[k][8w..8w+8), so each warp cp.async-stages its own slice into a private
// smem region -> the k-loop needs no __syncthreads, only wait+__syncwarp.
// EXACT ORDER CONTRACT: hg = sequential FFMA k=0..1023 from 0.0f;
// z = xg + hg (one rounded add). Gate math exact 0/1-integer arithmetic.
#define SM_W    (HID * 33)            // 33792 floats
#define SM_HS   (KC * BATCH)          // 8192 floats per buffer (8 warps x KC x 8)
#define SM_SPK  (BATCH * 33)          // 2112 floats
#define SMEM_BYTES ((SM_W + 2 * SM_HS + SM_SPK) * 4)   // 209152 B

extern __shared__ float sm[];

__global__ void __launch_bounds__(256, 1) spiking_lstm_rec(
    const float* __restrict__ h0, const float* __restrict__ c0,
    const float* __restrict__ Whh, float* __restrict__ y)
{
    float* w_sm = sm;                       // w_sm[k*33 + col]
    float* hs   = sm + SM_W;                // hs[buf][warp][k_local][8]
    float* spk  = sm + SM_W + 2 * SM_HS;    // spk[b*33 + col]

    const int cta  = blockIdx.x;
    const int u0   = cta * UPC;
    const int tid  = threadIdx.x;
    const int col  = tid & 31;     // gate = col/8, u_local = col%8
    const int wrp  = tid >> 5;     // warp id == bgrp: batch rows 8w..8w+8
    const int lane = tid & 31;
    const int ub   = tid & 7;
    const int bb   = tid >> 3;     // 0..31

    // ---- load W_hh slice into persistent smem (one time) ----
    {
        const int wc  = tid >> 3;                         // col 0..31
        const int sub = tid & 7;
        const int wrow = (wc >> 3) * HID + u0 + (wc & 7); // W_hh row for col wc
        const float* wp = Whh + (size_t)wrow * HID;
        for (int k0 = sub * 4; k0 < HID; k0 += 32) {
            float4 v = *(const float4*)&wp[k0];
            w_sm[(k0 + 0) * 33 + wc] = v.x;
            w_sm[(k0 + 1) * 33 + wc] = v.y;
            w_sm[(k0 + 2) * 33 + wc] = v.z;
            w_sm[(k0 + 3) * 33 + wc] = v.w;
        }
    }

    // ---- init c and transposed h[0] ----
    float c_a = c0[(size_t)bb * HID + u0 + ub];
    float c_b = c0[(size_t)(bb + 32) * HID + u0 + ub];
    __stcg(&g_h[0][u0 + ub][bb],      h0[(size_t)bb * HID + u0 + ub]);
    __stcg(&g_h[0][u0 + ub][bb + 32], h0[(size_t)(bb + 32) * HID + u0 + ub]);
    grid_barrier_atomic(NCTA2);   // h[0] visible; w_sm ready

    // per-warp staging geometry: lane stages k_locals [lane*4, lane*4+4)
    const int kl0 = lane * 4;

    for (int s = 0; s < T_STEPS; s++) {
        const float* __restrict__ hprev = &g_h[s & 1][0][0];

        // xg values (consumed at end of step; loads overlap all compute)
        float xgv[8];
        {
            size_t base = (size_t)s * BATCH * G4 + (size_t)((col >> 3) * HID + u0 + (col & 7));
#pragma unroll
            for (int r = 0; r < 8; r++)
                xgv[r] = __ldcg(&g_xg[base + (size_t)(wrp * 8 + r) * G4]);
        }

        float acc[8];
#pragma unroll
        for (int r = 0; r < 8; r++) acc[r] = 0.0f;

        // prefetch chunk 0 (warp-private slice: h[k][8w..8w+8))
        {
            const float* src = hprev + (size_t)kl0 * BATCH + wrp * 8;
            float* dst = hs + wrp * (KC * 8) + kl0 * 8;
#pragma unroll
            for (int j = 0; j < 4; j++) {
                cp_async_cg16(dst + j * 8,     src + j * BATCH);
                cp_async_cg16(dst + j * 8 + 4, src + j * BATCH + 4);
            }
            cp_async_commit();
        }

        for (int ic = 0; ic < HID / KC; ic++) {
            if (ic + 1 < HID / KC) {
                const float* src = hprev + (size_t)((ic + 1) * KC + kl0) * BATCH + wrp * 8;
                float* dst = hs + ((ic + 1) & 1) * SM_HS + wrp * (KC * 8) + kl0 * 8;
#pragma unroll
                for (int j = 0; j < 4; j++) {
                    cp_async_cg16(dst + j * 8,     src + j * BATCH);
                    cp_async_cg16(dst + j * 8 + 4, src + j * BATCH + 4);
                }
                cp_async_commit();
                cp_async_wait<1>();   // chunk ic complete, ic+1 in flight
            } else {
                cp_async_wait<0>();
            }
            __syncwarp();             // warp-local: staged slice visible

            const float* wk = w_sm + (ic * KC) * 33 + col;
            const float* hb = hs + (ic & 1) * SM_HS + wrp * (KC * 8);
#pragma unroll 8
            for (int k = 0; k < KC; k++) {
                float w = wk[k * 33];
                float4 p = *(const float4*)&hb[k * 8];      // broadcast
                float4 q = *(const float4*)&hb[k * 8 + 4];  // broadcast
                acc[0] = __fmaf_rn(p.x, w, acc[0]);
                acc[1] = __fmaf_rn(p.y, w, acc[1]);
                acc[2] = __fmaf_rn(p.z, w, acc[2]);
                acc[3] = __fmaf_rn(p.w, w, acc[3]);
                acc[4] = __fmaf_rn(q.x, w, acc[4]);
                acc[5] = __fmaf_rn(q.y, w, acc[5]);
                acc[6] = __fmaf_rn(q.z, w, acc[6]);
                acc[7] = __fmaf_rn(q.w, w, acc[7]);
            }
            __syncwarp();
        }

        // z = xg + hg; spike
#pragma unroll
        for (int r = 0; r < 8; r++) {
            float z = __fadd_rn(xgv[r], acc[r]);
            spk[(wrp * 8 + r) * 33 + col] = (z >= 0.0f) ? 1.0f : 0.0f;
        }
        __syncthreads();

        // gate update: c' = f*c + i*g ; h' = o*c'   (exact 0/1-integer math)
        {
            float* hnext = &g_h[(s + 1) & 1][0][0];

            float i1 = spk[bb * 33 + ub],      f1 = spk[bb * 33 + 8 + ub];
            float g1 = spk[bb * 33 + 16 + ub], o1 = spk[bb * 33 + 24 + ub];
            c_a = __fadd_rn(__fmul_rn(f1, c_a), __fmul_rn(i1, g1));
            float ha = __fmul_rn(o1, c_a);
            y[((size_t)s * BATCH + bb) * HID + u0 + ub] = ha;
            __stcg(&hnext[(size_t)(u0 + ub) * BATCH + bb], ha);

            float i2 = spk[(bb + 32) * 33 + ub],      f2 = spk[(bb + 32) * 33 + 8 + ub];
            float g2 = spk[(bb + 32) * 33 + 16 + ub], o2 = spk[(bb + 32) * 33 + 24 + ub];
            c_b = __fadd_rn(__fmul_rn(f2, c_b), __fmul_rn(i2, g2));
            float hb2 = __fmul_rn(o2, c_b);
            y[((size_t)s * BATCH + bb + 32) * HID + u0 + ub] = hb2;
            __stcg(&hnext[(size_t)(u0 + ub) * BATCH + bb + 32], hb2);
        }

        grid_barrier_atomic(NCTA2);
    }
}

// ---------------- launch ----------------------------------------------------
extern "C" void kernel_launch(void* const* d_in, const int* in_sizes, int n_in,
                              void* d_out, int out_size) {
    const float* x   = (const float*)d_in[0];   // [T,B,I]
    const float* h0  = (const float*)d_in[1];   // [B,H]
    const float* c0  = (const float*)d_in[2];   // [B,H]
    const float* Wih = (const float*)d_in[3];   // [4H,I]
    const float* bih = (const float*)d_in[4];   // [4H]
    const float* Whh = (const float*)d_in[5];   // [4H,H]
    const float* bhh = (const float*)d_in[6];   // [4H]
    float* y = (float*)d_out;                   // [T,B,H]

    cudaFuncSetAttribute(spiking_lstm_rec,
                         cudaFuncAttributeMaxDynamicSharedMemorySize, SMEM_BYTES);

    gemm_xproj<<<dim3(G4 / BN, (T_STEPS * BATCH) / BM), 256>>>(x, Wih, bih, bhh);
    spiking_lstm_rec<<<NCTA2, 256, SMEM_BYTES>>>(h0, c0, Whh, y);
}

// round 9
// speedup vs baseline: 1.1849x; 1.0362x over previous
#include <cuda_runtime.h>
#include <cstdint>

#define T_STEPS 256
#define BATCH   64
#define INDIM   1024
#define HID     1024
#define G4      4096
#define NCTA2   128   // recurrent CTAs (all co-resident)
#define UPC     8     // hidden units per recurrent CTA
#define KC      128   // k-chunk for h staging

// ---------------- scratch (static device globals; no allocs allowed) --------
__device__ float    g_xg[(size_t)T_STEPS * BATCH * G4];  // 256 MiB input projection
__device__ float    g_h[2][HID][BATCH];                  // TRANSPOSED [k][b], double buffered
__device__ unsigned g_bar_cnt;
__device__ unsigned g_bar_gen;
__device__ unsigned g_c1[8];          // two-level step barrier: group counters
__device__ unsigned g_c2;             // root counter
__device__ unsigned g_gen2;           // generation (== completed steps)
__device__ unsigned g_row_done[16];   // producer tile-row completion counters

// ---------------- init barrier (self-resetting, proven; used once) ----------
__device__ __forceinline__ void grid_barrier_atomic(unsigned nctas) {
    __syncthreads();
    __threadfence();
    if (threadIdx.x == 0) {
        unsigned gen = *(volatile unsigned*)&g_bar_gen;
        unsigned t = atomicAdd(&g_bar_cnt, 1u);
        if (t == nctas - 1u) {
            *(volatile unsigned*)&g_bar_cnt = 0u;
            __threadfence();
            atomicAdd(&g_bar_gen, 1u);
        } else {
            while (*(volatile unsigned*)&g_bar_gen == gen) { __nanosleep(64); }
        }
        __threadfence();
    }
    __syncthreads();
}

// ---------------- two-level per-step barrier (128 recurrent CTAs) -----------
// Monotonic counters, reset at launch start by CTA 0. 16 atomics/group in
// parallel + 8 root atomics vs 128 serialized before.
__device__ __forceinline__ void step_barrier(int cta, int s) {
    __syncthreads();
    __threadfence();
    if (threadIdx.x == 0) {
        unsigned t = atomicAdd(&g_c1[cta >> 4], 1u);
        if (t == 16u * (unsigned)(s + 1) - 1u) {          // last of group
            unsigned t2 = atomicAdd(&g_c2, 1u);
            if (t2 == 8u * (unsigned)(s + 1) - 1u)        // last group
                atomicAdd(&g_gen2, 1u);
        }
        unsigned v;
        do {
            asm volatile("ld.global.cg.u32 %0, [%1];" : "=r"(v) : "l"(&g_gen2));
            if (v < (unsigned)(s + 1)) __nanosleep(32);
        } while (v < (unsigned)(s + 1));
    }
    __threadfence();
    __syncthreads();
}

// ---------------- cp.async helpers ------------------------------------------
__device__ __forceinline__ void cp_async_cg16(void* dst_smem, const void* src) {
    unsigned d = (unsigned)__cvta_generic_to_shared(dst_smem);
    asm volatile("cp.async.cg.shared.global [%0], [%1], 16;\n" :: "r"(d), "l"(src));
}
__device__ __forceinline__ void cp_async_commit() {
    asm volatile("cp.async.commit_group;\n");
}
template <int N>
__device__ __forceinline__ void cp_async_wait() {
    asm volatile("cp.async.wait_group %0;\n" :: "n"(N));
}

// ---------------- GEMM tile body (EXACT ORDER CONTRACT) ---------------------
// Per output element: single fp32 accumulator, sequential fused-FMA over
// k = 0..1023 ascending, then +b_ih, then +b_hh. Scalar FFMA only.
#define BM 128
#define BN 128
#define BK 8

__device__ __forceinline__ void gemm_tile_body(
    const float* __restrict__ x, const float* __restrict__ Wih,
    const float* __restrict__ bih, const float* __restrict__ bhh,
    int m0, int n0, float* As, float* Bs, bool cg_store)
{
    const int tid = threadIdx.x;
    const int tm  = tid >> 4;       // 0..15
    const int tn  = tid & 15;       // 0..15
    const int lk  = tid & 7;        // k lane
    const int lr  = tid >> 3;       // row lane (0..31)

    float acc[8][8];
#pragma unroll
    for (int i = 0; i < 8; i++)
#pragma unroll
        for (int j = 0; j < 8; j++) acc[i][j] = 0.0f;

    float ra[4], rb[4];
#pragma unroll
    for (int p = 0; p < 4; p++) {
        ra[p] = x  [(size_t)(m0 + lr + p * 32) * INDIM + lk];
        rb[p] = Wih[(size_t)(n0 + lr + p * 32) * INDIM + lk];
    }

    for (int it = 0; it < INDIM / BK; it++) {
        const int buf = it & 1;
        float* Ab = As + (buf * BK) * 132;
        float* Bb = Bs + (buf * BK) * 132;
#pragma unroll
        for (int p = 0; p < 4; p++) {
            Ab[lk * 132 + lr + p * 32] = ra[p];
            Bb[lk * 132 + lr + p * 32] = rb[p];
        }
        __syncthreads();

        if (it + 1 < INDIM / BK) {
            const int k0 = (it + 1) * BK;
#pragma unroll
            for (int p = 0; p < 4; p++) {
                ra[p] = x  [(size_t)(m0 + lr + p * 32) * INDIM + k0 + lk];
                rb[p] = Wih[(size_t)(n0 + lr + p * 32) * INDIM + k0 + lk];
            }
        }

#pragma unroll
        for (int k = 0; k < BK; k++) {
            float4 a0 = *(const float4*)&Ab[k * 132 + tm * 8];
            float4 a1 = *(const float4*)&Ab[k * 132 + tm * 8 + 4];
            float4 b0 = *(const float4*)&Bb[k * 132 + tn * 8];
            float4 b1 = *(const float4*)&Bb[k * 132 + tn * 8 + 4];
            float av[8] = {a0.x, a0.y, a0.z, a0.w, a1.x, a1.y, a1.z, a1.w};
            float bv[8] = {b0.x, b0.y, b0.z, b0.w, b1.x, b1.y, b1.z, b1.w};
#pragma unroll
            for (int i = 0; i < 8; i++)
#pragma unroll
                for (int j = 0; j < 8; j++)
                    acc[i][j] = __fmaf_rn(av[i], bv[j], acc[i][j]);
        }
    }

    float bi[8], bh[8];
#pragma unroll
    for (int j = 0; j < 8; j++) {
        int n = n0 + tn * 8 + j;
        bi[j] = bih[n];
        bh[j] = bhh[n];
    }
#pragma unroll
    for (int i = 0; i < 8; i++) {
        float v[8];
#pragma unroll
        for (int j = 0; j < 8; j++)
            v[j] = __fadd_rn(__fadd_rn(acc[i][j], bi[j]), bh[j]);
        size_t row = (size_t)(m0 + tm * 8 + i) * G4 + (n0 + tn * 8);
        float4 v0 = make_float4(v[0], v[1], v[2], v[3]);
        float4 v1 = make_float4(v[4], v[5], v[6], v[7]);
        if (cg_store) {
            __stcg((float4*)&g_xg[row],     v0);
            __stcg((float4*)&g_xg[row + 4], v1);
        } else {
            *(float4*)&g_xg[row]     = v0;
            *(float4*)&g_xg[row + 4] = v1;
        }
    }
}

// ---------------- Phase 1 standalone: steps [0, S0) -------------------------
__global__ void __launch_bounds__(256, 2) gemm_xproj(
    const float* __restrict__ x, const float* __restrict__ Wih,
    const float* __restrict__ bih, const float* __restrict__ bhh)
{
    __shared__ float As[2 * BK * 132];
    __shared__ float Bs[2 * BK * 132];
    gemm_tile_body(x, Wih, bih, bhh,
                   blockIdx.y * BM, blockIdx.x * BN, As, Bs, false);
}

// ---------------- Fused persistent kernel -----------------------------------
// CTAs [0,128): recurrence (identical math to round 8).
// CTAs [128,128+P): producers computing xg for steps [S0,256), signaling
// per-tile-row (= 2 steps) completion via g_row_done.
#define SM_W    (HID * 33)            // 33792 floats
#define SM_HS   (KC * BATCH)          // 8192 floats per buffer
#define SM_SPK  (BATCH * 33)
#define SMEM_BYTES ((SM_W + 2 * SM_HS + SM_SPK) * 4)   // 209152 B

extern __shared__ float sm[];

__global__ void __launch_bounds__(256, 1) spiking_fused(
    const float* __restrict__ h0, const float* __restrict__ c0,
    const float* __restrict__ Whh, float* __restrict__ y,
    const float* __restrict__ x, const float* __restrict__ Wih,
    const float* __restrict__ bih, const float* __restrict__ bhh,
    int P, int S0)
{
    const int cta = blockIdx.x;
    const int tid = threadIdx.x;
    const unsigned nall = (unsigned)(NCTA2 + P);

    // ---- launch-start resets (CTA 0; ordered by init barrier) ----
    if (cta == 0) {
        if (tid < 8)  g_c1[tid] = 0u;
        if (tid == 8) g_c2 = 0u;
        if (tid == 9) g_gen2 = 0u;
        if (tid >= 16 && tid < 32) g_row_done[tid - 16] = 0u;
    }

    // =================== PRODUCER ROLE ===================
    if (cta >= NCTA2) {
        grid_barrier_atomic(nall);
        const int pid  = cta - NCTA2;
        const int rows = (T_STEPS - S0) / 2;      // tile-rows (2 steps each)
        float* As = sm;
        float* Bs = sm + 2 * BK * 132;
        for (int t = 0; t < rows * 32; t++) {
            if (t % P != pid) continue;
            const int r  = t >> 5;
            const int ct = t & 31;
            gemm_tile_body(x, Wih, bih, bhh,
                           S0 * BATCH + r * BM, ct * BN, As, Bs, true);
            __syncthreads();
            __threadfence();
            if (tid == 0) atomicAdd(&g_row_done[r], 1u);
            __syncthreads();
        }
        return;
    }

    // =================== RECURRENT ROLE ===================
    float* w_sm = sm;                       // w_sm[k*33 + col]
    float* hs   = sm + SM_W;                // hs[buf][warp][k_local][8]
    float* spk  = sm + SM_W + 2 * SM_HS;    // spk[b*33 + col]

    const int u0   = cta * UPC;
    const int col  = tid & 31;     // gate = col/8, u_local = col%8
    const int wrp  = tid >> 5;     // warp id == bgrp
    const int lane = tid & 31;
    const int ub   = tid & 7;
    const int bb   = tid >> 3;     // 0..31

    // ---- load W_hh slice into persistent smem (one time) ----
    {
        const int wc  = tid >> 3;
        const int sub = tid & 7;
        const int wrow = (wc >> 3) * HID + u0 + (wc & 7);
        const float* wp = Whh + (size_t)wrow * HID;
        for (int k0 = sub * 4; k0 < HID; k0 += 32) {
            float4 v = *(const float4*)&wp[k0];
            w_sm[(k0 + 0) * 33 + wc] = v.x;
            w_sm[(k0 + 1) * 33 + wc] = v.y;
            w_sm[(k0 + 2) * 33 + wc] = v.z;
            w_sm[(k0 + 3) * 33 + wc] = v.w;
        }
    }

    float c_a = c0[(size_t)bb * HID + u0 + ub];
    float c_b = c0[(size_t)(bb + 32) * HID + u0 + ub];
    __stcg(&g_h[0][u0 + ub][bb],      h0[(size_t)bb * HID + u0 + ub]);
    __stcg(&g_h[0][u0 + ub][bb + 32], h0[(size_t)(bb + 32) * HID + u0 + ub]);
    grid_barrier_atomic(nall);   // h[0] + resets visible; w_sm ready

    const int kl0 = lane * 4;    // per-warp staging: lane stages 4 k_locals

    for (int s = 0; s < T_STEPS; s++) {
        // gate on producer output for late steps (normally pre-satisfied)
        if (s >= S0) {
            if (tid == 0) {
                unsigned v;
                const unsigned* f = &g_row_done[(s - S0) >> 1];
                do {
                    asm volatile("ld.global.cg.u32 %0, [%1];" : "=r"(v) : "l"(f));
                    if (v < 32u) __nanosleep(128);
                } while (v < 32u);
            }
            __syncthreads();
        }

        const float* __restrict__ hprev = &g_h[s & 1][0][0];

        float xgv[8];
        {
            size_t base = (size_t)s * BATCH * G4 + (size_t)((col >> 3) * HID + u0 + (col & 7));
#pragma unroll
            for (int r = 0; r < 8; r++)
                xgv[r] = __ldcg(&g_xg[base + (size_t)(wrp * 8 + r) * G4]);
        }

        float acc[8];
#pragma unroll
        for (int r = 0; r < 8; r++) acc[r] = 0.0f;

        // prefetch chunk 0 (warp-private slice h[k][8w..8w+8))
        {
            const float* src = hprev + (size_t)kl0 * BATCH + wrp * 8;
            float* dst = hs + wrp * (KC * 8) + kl0 * 8;
#pragma unroll
            for (int j = 0; j < 4; j++) {
                cp_async_cg16(dst + j * 8,     src + j * BATCH);
                cp_async_cg16(dst + j * 8 + 4, src + j * BATCH + 4);
            }
            cp_async_commit();
        }

        for (int ic = 0; ic < HID / KC; ic++) {
            if (ic + 1 < HID / KC) {
                const float* src = hprev + (size_t)((ic + 1) * KC + kl0) * BATCH + wrp * 8;
                float* dst = hs + ((ic + 1) & 1) * SM_HS + wrp * (KC * 8) + kl0 * 8;
#pragma unroll
                for (int j = 0; j < 4; j++) {
                    cp_async_cg16(dst + j * 8,     src + j * BATCH);
                    cp_async_cg16(dst + j * 8 + 4, src + j * BATCH + 4);
                }
                cp_async_commit();
                cp_async_wait<1>();
            } else {
                cp_async_wait<0>();
            }
            __syncwarp();

            const float* wk = w_sm + (ic * KC) * 33 + col;
            const float* hb = hs + (ic & 1) * SM_HS + wrp * (KC * 8);
#pragma unroll 8
            for (int k = 0; k < KC; k++) {
                float w = wk[k * 33];
                float4 p = *(const float4*)&hb[k * 8];
                float4 q = *(const float4*)&hb[k * 8 + 4];
                acc[0] = __fmaf_rn(p.x, w, acc[0]);
                acc[1] = __fmaf_rn(p.y, w, acc[1]);
                acc[2] = __fmaf_rn(p.z, w, acc[2]);
                acc[3] = __fmaf_rn(p.w, w, acc[3]);
                acc[4] = __fmaf_rn(q.x, w, acc[4]);
                acc[5] = __fmaf_rn(q.y, w, acc[5]);
                acc[6] = __fmaf_rn(q.z, w, acc[6]);
                acc[7] = __fmaf_rn(q.w, w, acc[7]);
            }
            __syncwarp();
        }

        // z = xg + hg; spike
#pragma unroll
        for (int r = 0; r < 8; r++) {
            float z = __fadd_rn(xgv[r], acc[r]);
            spk[(wrp * 8 + r) * 33 + col] = (z >= 0.0f) ? 1.0f : 0.0f;
        }
        __syncthreads();

        // gate update: c' = f*c + i*g ; h' = o*c'  (exact 0/1-integer math)
        {
            float* hnext = &g_h[(s + 1) & 1][0][0];

            float i1 = spk[bb * 33 + ub],      f1 = spk[bb * 33 + 8 + ub];
            float g1 = spk[bb * 33 + 16 + ub], o1 = spk[bb * 33 + 24 + ub];
            c_a = __fadd_rn(__fmul_rn(f1, c_a), __fmul_rn(i1, g1));
            float ha = __fmul_rn(o1, c_a);
            y[((size_t)s * BATCH + bb) * HID + u0 + ub] = ha;
            __stcg(&hnext[(size_t)(u0 + ub) * BATCH + bb], ha);

            float i2 = spk[(bb + 32) * 33 + ub],      f2 = spk[(bb + 32) * 33 + 8 + ub];
            float g2 = spk[(bb + 32) * 33 + 16 + ub], o2 = spk[(bb + 32) * 33 + 24 + ub];
            c_b = __fadd_rn(__fmul_rn(f2, c_b), __fmul_rn(i2, g2));
            float hb2 = __fmul_rn(o2, c_b);
            y[((size_t)s * BATCH + bb + 32) * HID + u0 + ub] = hb2;
            __stcg(&hnext[(size_t)(u0 + ub) * BATCH + bb + 32], hb2);
        }

        step_barrier(cta, s);
    }
}

// ---------------- launch ----------------------------------------------------
extern "C" void kernel_launch(void* const* d_in, const int* in_sizes, int n_in,
                              void* d_out, int out_size) {
    const float* x   = (const float*)d_in[0];   // [T,B,I]
    const float* h0  = (const float*)d_in[1];   // [B,H]
    const float* c0  = (const float*)d_in[2];   // [B,H]
    const float* Wih = (const float*)d_in[3];   // [4H,I]
    const float* bih = (const float*)d_in[4];   // [4H]
    const float* Whh = (const float*)d_in[5];   // [4H,H]
    const float* bhh = (const float*)d_in[6];   // [4H]
    float* y = (float*)d_out;                   // [T,B,H]

    // producer count from SM count (capture-time constant, deterministic)
    int sms = 0;
    cudaDeviceGetAttribute(&sms, cudaDevAttrMultiProcessorCount, 0);
    int P = sms - NCTA2;
    if (P > 20) P = 20;
    int PS = (P >= 16) ? 32 : (P >= 8 ? 16 : 0);
    if (PS == 0) P = 0;
    const int S0 = T_STEPS - PS;

    cudaFuncSetAttribute(spiking_fused,
                         cudaFuncAttributeMaxDynamicSharedMemorySize, SMEM_BYTES);

    // phase 1 for steps [0, S0): grid.y = S0*64/128 = S0/2
    gemm_xproj<<<dim3(G4 / BN, S0 / 2), 256>>>(x, Wih, bih, bhh);
    spiking_fused<<<NCTA2 + P, 256, SMEM_BYTES>>>(h0, c0, Whh, y,
                                                  x, Wih, bih, bhh, P, S0);
}

// round 13
// speedup vs baseline: 1.2237x; 1.0328x over previous
#include <cuda_runtime.h>
#include <cstdint>

#define T_STEPS 256
#define BATCH   64
#define INDIM   1024
#define HID     1024
#define G4      4096
#define NCTA2   128   // recurrent CTAs (all co-resident)
#define UPC     8     // hidden units per recurrent CTA
#define KC      128   // k-chunk for h staging
#define MAXROWS 24    // max producer tile-rows (PS=48 -> 24 rows)

// ---------------- scratch (static device globals; no allocs allowed) --------
__device__ float    g_xg[(size_t)T_STEPS * BATCH * G4];  // 256 MiB input projection
__device__ float    g_h[2][HID][BATCH];                  // TRANSPOSED [k][b], double buffered
__device__ unsigned g_bar_cnt;
__device__ unsigned g_bar_gen;
__device__ unsigned g_c1[8];            // two-level step barrier: group counters
__device__ unsigned g_c2;               // root counter
__device__ unsigned g_gen2;             // generation (== completed steps)
__device__ unsigned g_row_done[MAXROWS];// producer tile-row completion counters

// ---------------- init barrier (self-resetting, proven; used once) ----------
__device__ __forceinline__ void grid_barrier_atomic(unsigned nctas) {
    __syncthreads();
    __threadfence();
    if (threadIdx.x == 0) {
        unsigned gen = *(volatile unsigned*)&g_bar_gen;
        unsigned t = atomicAdd(&g_bar_cnt, 1u);
        if (t == nctas - 1u) {
            *(volatile unsigned*)&g_bar_cnt = 0u;
            __threadfence();
            atomicAdd(&g_bar_gen, 1u);
        } else {
            while (*(volatile unsigned*)&g_bar_gen == gen) { __nanosleep(64); }
        }
        __threadfence();
    }
    __syncthreads();
}

// ---------------- two-level per-step barrier (128 recurrent CTAs) -----------
__device__ __forceinline__ void step_barrier(int cta, int s) {
    __syncthreads();
    __threadfence();
    if (threadIdx.x == 0) {
        unsigned t = atomicAdd(&g_c1[cta >> 4], 1u);
        if (t == 16u * (unsigned)(s + 1) - 1u) {          // last of group
            unsigned t2 = atomicAdd(&g_c2, 1u);
            if (t2 == 8u * (unsigned)(s + 1) - 1u)        // last group
                atomicAdd(&g_gen2, 1u);
        }
        unsigned v;
        do {
            asm volatile("ld.global.cg.u32 %0, [%1];" : "=r"(v) : "l"(&g_gen2));
            if (v < (unsigned)(s + 1)) __nanosleep(32);
        } while (v < (unsigned)(s + 1));
    }
    __threadfence();
    __syncthreads();
}

// ---------------- cp.async helpers ------------------------------------------
__device__ __forceinline__ void cp_async_cg16(void* dst_smem, const void* src) {
    unsigned d = (unsigned)__cvta_generic_to_shared(dst_smem);
    asm volatile("cp.async.cg.shared.global [%0], [%1], 16;\n" :: "r"(d), "l"(src));
}
__device__ __forceinline__ void cp_async_commit() {
    asm volatile("cp.async.commit_group;\n");
}
template <int N>
__device__ __forceinline__ void cp_async_wait() {
    asm volatile("cp.async.wait_group %0;\n" :: "n"(N));
}

// ---------------- GEMM tile body (EXACT ORDER CONTRACT) ---------------------
// Per output element: single fp32 accumulator, sequential fused-FMA over
// k = 0..1023 ascending, then +b_ih, then +b_hh. Scalar FFMA only.
// BK=16: 1024 SMSP-cycles of compute per sync / per prefetch window.
#define BM 128
#define BN 128
#define BK 16

__device__ __forceinline__ void gemm_tile_body(
    const float* __restrict__ x, const float* __restrict__ Wih,
    const float* __restrict__ bih, const float* __restrict__ bhh,
    int m0, int n0, float* As, float* Bs, bool cg_store)
{
    const int tid = threadIdx.x;
    const int tm  = tid >> 4;       // 0..15
    const int tn  = tid & 15;       // 0..15
    const int lk  = tid & 15;       // k lane (0..15)
    const int lr  = tid >> 4;       // row lane (0..15)

    float acc[8][8];
#pragma unroll
    for (int i = 0; i < 8; i++)
#pragma unroll
        for (int j = 0; j < 8; j++) acc[i][j] = 0.0f;

    float ra[8], rb[8];
#pragma unroll
    for (int p = 0; p < 8; p++) {
        ra[p] = x  [(size_t)(m0 + lr + p * 16) * INDIM + lk];
        rb[p] = Wih[(size_t)(n0 + lr + p * 16) * INDIM + lk];
    }

    for (int it = 0; it < INDIM / BK; it++) {
        const int buf = it & 1;
        float* Ab = As + (buf * BK) * 132;
        float* Bb = Bs + (buf * BK) * 132;
#pragma unroll
        for (int p = 0; p < 8; p++) {
            Ab[lk * 132 + lr + p * 16] = ra[p];
            Bb[lk * 132 + lr + p * 16] = rb[p];
        }
        __syncthreads();

        if (it + 1 < INDIM / BK) {
            const int k0 = (it + 1) * BK;
#pragma unroll
            for (int p = 0; p < 8; p++) {
                ra[p] = x  [(size_t)(m0 + lr + p * 16) * INDIM + k0 + lk];
                rb[p] = Wih[(size_t)(n0 + lr + p * 16) * INDIM + k0 + lk];
            }
        }

#pragma unroll
        for (int k = 0; k < BK; k++) {
            float4 a0 = *(const float4*)&Ab[k * 132 + tm * 8];
            float4 a1 = *(const float4*)&Ab[k * 132 + tm * 8 + 4];
            float4 b0 = *(const float4*)&Bb[k * 132 + tn * 8];
            float4 b1 = *(const float4*)&Bb[k * 132 + tn * 8 + 4];
            float av[8] = {a0.x, a0.y, a0.z, a0.w, a1.x, a1.y, a1.z, a1.w};
            float bv[8] = {b0.x, b0.y, b0.z, b0.w, b1.x, b1.y, b1.z, b1.w};
#pragma unroll
            for (int i = 0; i < 8; i++)
#pragma unroll
                for (int j = 0; j < 8; j++)
                    acc[i][j] = __fmaf_rn(av[i], bv[j], acc[i][j]);
        }
        __syncthreads();
    }

    float bi[8], bh[8];
#pragma unroll
    for (int j = 0; j < 8; j++) {
        int n = n0 + tn * 8 + j;
        bi[j] = bih[n];
        bh[j] = bhh[n];
    }
#pragma unroll
    for (int i = 0; i < 8; i++) {
        float v[8];
#pragma unroll
        for (int j = 0; j < 8; j++)
            v[j] = __fadd_rn(__fadd_rn(acc[i][j], bi[j]), bh[j]);
        size_t row = (size_t)(m0 + tm * 8 + i) * G4 + (n0 + tn * 8);
        float4 v0 = make_float4(v[0], v[1], v[2], v[3]);
        float4 v1 = make_float4(v[4], v[5], v[6], v[7]);
        if (cg_store) {
            __stcg((float4*)&g_xg[row],     v0);
            __stcg((float4*)&g_xg[row + 4], v1);
        } else {
            *(float4*)&g_xg[row]     = v0;
            *(float4*)&g_xg[row + 4] = v1;
        }
    }
}

// ---------------- Phase 1 standalone: steps [0, S0) -------------------------
__global__ void __launch_bounds__(256, 2) gemm_xproj(
    const float* __restrict__ x, const float* __restrict__ Wih,
    const float* __restrict__ bih, const float* __restrict__ bhh)
{
    __shared__ float As[2 * BK * 132];
    __shared__ float Bs[2 * BK * 132];
    gemm_tile_body(x, Wih, bih, bhh,
                   blockIdx.y * BM, blockIdx.x * BN, As, Bs, false);
}

// ---------------- Fused persistent kernel -----------------------------------
// CTAs [0,128): recurrence. CTAs [128,128+P): producers for steps [S0,256).
#define SM_W    (HID * 33)            // 33792 floats
#define SM_HS   (KC * BATCH)          // 8192 floats per buffer
#define SM_SPK  (BATCH * 33)
#define SMEM_BYTES ((SM_W + 2 * SM_HS + SM_SPK) * 4)   // 209152 B

extern __shared__ float sm[];

__global__ void __launch_bounds__(256, 1) spiking_fused(
    const float* __restrict__ h0, const float* __restrict__ c0,
    const float* __restrict__ Whh, float* __restrict__ y,
    const float* __restrict__ x, const float* __restrict__ Wih,
    const float* __restrict__ bih, const float* __restrict__ bhh,
    int P, int S0)
{
    const int cta = blockIdx.x;
    const int tid = threadIdx.x;
    const unsigned nall = (unsigned)(NCTA2 + P);

    // ---- launch-start resets (CTA 0; ordered by init barrier) ----
    if (cta == 0) {
        if (tid < 8)  g_c1[tid] = 0u;
        if (tid == 8) g_c2 = 0u;
        if (tid == 9) g_gen2 = 0u;
        if (tid >= 16 && tid < 16 + MAXROWS) g_row_done[tid - 16] = 0u;
    }

    // =================== PRODUCER ROLE ===================
    if (cta >= NCTA2) {
        grid_barrier_atomic(nall);
        const int pid  = cta - NCTA2;
        const int rows = (T_STEPS - S0) / 2;      // tile-rows (2 steps each)
        float* As = sm;
        float* Bs = sm + 2 * BK * 132;
        for (int t = 0; t < rows * 32; t++) {
            if (t % P != pid) continue;
            const int r  = t >> 5;
            const int ct = t & 31;
            gemm_tile_body(x, Wih, bih, bhh,
                           S0 * BATCH + r * BM, ct * BN, As, Bs, true);
            __syncthreads();
            __threadfence();
            if (tid == 0) atomicAdd(&g_row_done[r], 1u);
            __syncthreads();
        }
        return;
    }

    // =================== RECURRENT ROLE ===================
    float* w_sm = sm;                       // w_sm[k*33 + col]
    float* hs   = sm + SM_W;                // hs[buf][warp][k_local][8]
    float* spk  = sm + SM_W + 2 * SM_HS;    // spk[b*33 + col]

    const int u0   = cta * UPC;
    const int col  = tid & 31;     // gate = col/8, u_local = col%8
    const int wrp  = tid >> 5;     // warp id == bgrp
    const int lane = tid & 31;
    const int ub   = tid & 7;
    const int bb   = tid >> 3;     // 0..31

    // ---- load W_hh slice into persistent smem (one time) ----
    {
        const int wc  = tid >> 3;
        const int sub = tid & 7;
        const int wrow = (wc >> 3) * HID + u0 + (wc & 7);
        const float* wp = Whh + (size_t)wrow * HID;
        for (int k0 = sub * 4; k0 < HID; k0 += 32) {
            float4 v = *(const float4*)&wp[k0];
            w_sm[(k0 + 0) * 33 + wc] = v.x;
            w_sm[(k0 + 1) * 33 + wc] = v.y;
            w_sm[(k0 + 2) * 33 + wc] = v.z;
            w_sm[(k0 + 3) * 33 + wc] = v.w;
        }
    }

    float c_a = c0[(size_t)bb * HID + u0 + ub];
    float c_b = c0[(size_t)(bb + 32) * HID + u0 + ub];
    __stcg(&g_h[0][u0 + ub][bb],      h0[(size_t)bb * HID + u0 + ub]);
    __stcg(&g_h[0][u0 + ub][bb + 32], h0[(size_t)(bb + 32) * HID + u0 + ub]);
    grid_barrier_atomic(nall);   // h[0] + resets visible; w_sm ready

    const int kl0 = lane * 4;    // per-warp staging: lane stages 4 k_locals

    for (int s = 0; s < T_STEPS; s++) {
        // gate on producer output for late steps (normally pre-satisfied)
        if (s >= S0) {
            if (tid == 0) {
                unsigned v;
                const unsigned* f = &g_row_done[(s - S0) >> 1];
                do {
                    asm volatile("ld.global.cg.u32 %0, [%1];" : "=r"(v) : "l"(f));
                    if (v < 32u) __nanosleep(128);
                } while (v < 32u);
            }
            __syncthreads();
        }

        const float* __restrict__ hprev = &g_h[s & 1][0][0];

        float xgv[8];
        {
            size_t base = (size_t)s * BATCH * G4 + (size_t)((col >> 3) * HID + u0 + (col & 7));
#pragma unroll
            for (int r = 0; r < 8; r++)
                xgv[r] = __ldcg(&g_xg[base + (size_t)(wrp * 8 + r) * G4]);
        }

        float acc[8];
#pragma unroll
        for (int r = 0; r < 8; r++) acc[r] = 0.0f;

        // prefetch chunk 0 (warp-private slice h[k][8w..8w+8))
        {
            const float* src = hprev + (size_t)kl0 * BATCH + wrp * 8;
            float* dst = hs + wrp * (KC * 8) + kl0 * 8;
#pragma unroll
            for (int j = 0; j < 4; j++) {
                cp_async_cg16(dst + j * 8,     src + j * BATCH);
                cp_async_cg16(dst + j * 8 + 4, src + j * BATCH + 4);
            }
            cp_async_commit();
        }

        for (int ic = 0; ic < HID / KC; ic++) {
            if (ic + 1 < HID / KC) {
                const float* src = hprev + (size_t)((ic + 1) * KC + kl0) * BATCH + wrp * 8;
                float* dst = hs + ((ic + 1) & 1) * SM_HS + wrp * (KC * 8) + kl0 * 8;
#pragma unroll
                for (int j = 0; j < 4; j++) {
                    cp_async_cg16(dst + j * 8,     src + j * BATCH);
                    cp_async_cg16(dst + j * 8 + 4, src + j * BATCH + 4);
                }
                cp_async_commit();
                cp_async_wait<1>();
            } else {
                cp_async_wait<0>();
            }
            __syncwarp();

            const float* wk = w_sm + (ic * KC) * 33 + col;
            const float* hb = hs + (ic & 1) * SM_HS + wrp * (KC * 8);
#pragma unroll 8
            for (int k = 0; k < KC; k++) {
                float w = wk[k * 33];
                float4 p = *(const float4*)&hb[k * 8];
                float4 q = *(const float4*)&hb[k * 8 + 4];
                acc[0] = __fmaf_rn(p.x, w, acc[0]);
                acc[1] = __fmaf_rn(p.y, w, acc[1]);
                acc[2] = __fmaf_rn(p.z, w, acc[2]);
                acc[3] = __fmaf_rn(p.w, w, acc[3]);
                acc[4] = __fmaf_rn(q.x, w, acc[4]);
                acc[5] = __fmaf_rn(q.y, w, acc[5]);
                acc[6] = __fmaf_rn(q.z, w, acc[6]);
                acc[7] = __fmaf_rn(q.w, w, acc[7]);
            }
            __syncwarp();
        }

        // z = xg + hg; spike
#pragma unroll
        for (int r = 0; r < 8; r++) {
            float z = __fadd_rn(xgv[r], acc[r]);
            spk[(wrp * 8 + r) * 33 + col] = (z >= 0.0f) ? 1.0f : 0.0f;
        }
        __syncthreads();

        // gate update: c' = f*c + i*g ; h' = o*c'  (exact 0/1-integer math)
        {
            float* hnext = &g_h[(s + 1) & 1][0][0];

            float i1 = spk[bb * 33 + ub],      f1 = spk[bb * 33 + 8 + ub];
            float g1 = spk[bb * 33 + 16 + ub], o1 = spk[bb * 33 + 24 + ub];
            c_a = __fadd_rn(__fmul_rn(f1, c_a), __fmul_rn(i1, g1));
            float ha = __fmul_rn(o1, c_a);
            y[((size_t)s * BATCH + bb) * HID + u0 + ub] = ha;
            __stcg(&hnext[(size_t)(u0 + ub) * BATCH + bb], ha);

            float i2 = spk[(bb + 32) * 33 + ub],      f2 = spk[(bb + 32) * 33 + 8 + ub];
            float g2 = spk[(bb + 32) * 33 + 16 + ub], o2 = spk[(bb + 32) * 33 + 24 + ub];
            c_b = __fadd_rn(__fmul_rn(f2, c_b), __fmul_rn(i2, g2));
            float hb2 = __fmul_rn(o2, c_b);
            y[((size_t)s * BATCH + bb + 32) * HID + u0 + ub] = hb2;
            __stcg(&hnext[(size_t)(u0 + ub) * BATCH + bb + 32], hb2);
        }

        step_barrier(cta, s);
    }
}

// ---------------- launch ----------------------------------------------------
extern "C" void kernel_launch(void* const* d_in, const int* in_sizes, int n_in,
                              void* d_out, int out_size) {
    const float* x   = (const float*)d_in[0];   // [T,B,I]
    const float* h0  = (const float*)d_in[1];   // [B,H]
    const float* c0  = (const float*)d_in[2];   // [B,H]
    const float* Wih = (const float*)d_in[3];   // [4H,I]
    const float* bih = (const float*)d_in[4];   // [4H]
    const float* Whh = (const float*)d_in[5];   // [4H,H]
    const float* bhh = (const float*)d_in[6];   // [4H]
    float* y = (float*)d_out;                   // [T,B,H]

    int sms = 0;
    cudaDeviceGetAttribute(&sms, cudaDevAttrMultiProcessorCount, 0);
    int P = sms - NCTA2;
    if (P > 20) P = 20;
    int PS = (P >= 16) ? 48 : (P >= 8 ? 16 : 0);
    if (PS == 0) P = 0;
    const int S0 = T_STEPS - PS;

    cudaFuncSetAttribute(spiking_fused,
                         cudaFuncAttributeMaxDynamicSharedMemorySize, SMEM_BYTES);

    gemm_xproj<<<dim3(G4 / BN, S0 / 2), 256>>>(x, Wih, bih, bhh);
    spiking_fused<<<NCTA2 + P, 256, SMEM_BYTES>>>(h0, c0, Whh, y,
                                                  x, Wih, bih, bhh, P, S0);
}